// round 8
// baseline (speedup 1.0000x reference)
#include <cuda_runtime.h>
#include <cuda_bf16.h>

// AngleTensor: out[b,i,j,k] = mask * arccos( u_ij . u_ik ),  u_ij = (p_j-p_i)/d_ij
// B=8, N=128 fixed.  grid=(N,B), 256 threads/block (one block per (b,i)).
//
// Execution shape: thread t owns k = 4*(t&31)..+3 (32 contiguous lanes x float4
// -> one 512B coalesced STG per warp); j phase = t>>5 (0..7), step 8, 16 iters.
// 8 warps/block share ONE prologue + shared tile (vs R3's duplicated-prologue
// z-split): warps 4096 -> 8192, occupancy ceiling ~31% -> ~75%.
// Masked entries (row j==i, col k==i, diag j==k) zeroed by post-sync fixup.
// acos via A&S 4.4.45 rebased in y = 1-|c|; sign handled branch/predicate-free:
//   b = sqrt(y)*q(y) in [0, pi/2];  acos(c) = pi/2 - orsign(pi/2 - b, c)
// where orsign(v, c) = v with c's sign bit ORed in (one LOP3).

#define N_FIXED 128
#define PI_F    3.14159265358979f
#define HALFPI  1.57079632679490f

__device__ __forceinline__ float orsign(float v, float c) {
    // v >= 0; returns v with the sign bit of c copied in (|v| * sign(c) for v>=0)
    return __uint_as_float(__float_as_uint(v) | (__float_as_uint(c) & 0x80000000u));
}

__global__ __launch_bounds__(256) void angle_kernel(
    const float* __restrict__ pos,   // (B, N, 3)
    const float* __restrict__ dist,  // (B, N, N)
    float* __restrict__ out)         // (B, N, N, N)
{
    const int i = blockIdx.x;
    const int b = blockIdx.y;
    const int t = threadIdx.x;
    const int N = N_FIXED;

    __shared__ float4 sh[N_FIXED];   // unit vectors

    const float pix = pos[(b * N + i) * 3 + 0];
    const float piy = pos[(b * N + i) * 3 + 1];
    const float piz = pos[(b * N + i) * 3 + 2];

    if (t < N) {
        const int j = t;
        const float px = pos[(b * N + j) * 3 + 0];
        const float py = pos[(b * N + j) * 3 + 1];
        const float pz = pos[(b * N + j) * 3 + 2];
        const float d  = dist[((size_t)b * N + i) * N + j];
        const float inv = (d > 0.0f) ? (1.0f / d) : 0.0f;  // zero vec on j==i
        sh[j] = make_float4((px - pix) * inv, (py - piy) * inv, (pz - piz) * inv, 0.0f);
    }
    __syncthreads();

    const int k0 = (t & 31) * 4;   // owns k0..k0+3
    const int jq = t >> 5;         // j phase 0..7 (warp-uniform)

    const float4 u0 = sh[k0 + 0];
    const float4 u1 = sh[k0 + 1];
    const float4 u2 = sh[k0 + 2];
    const float4 u3 = sh[k0 + 3];

    float* orow = out + (((size_t)b * N + i) * N) * N;
    float* o = orow + (size_t)jq * N + k0;   // strength-reduced store cursor

#pragma unroll 4
    for (int j = jq; j < N; j += 8) {
        const float4 uj = sh[j];

        float c0 = uj.x * u0.x; c0 = fmaf(uj.y, u0.y, c0); c0 = fmaf(uj.z, u0.z, c0);
        float c1 = uj.x * u1.x; c1 = fmaf(uj.y, u1.y, c1); c1 = fmaf(uj.z, u1.z, c1);
        float c2 = uj.x * u2.x; c2 = fmaf(uj.y, u2.y, c2); c2 = fmaf(uj.z, u2.z, c2);
        float c3 = uj.x * u3.x; c3 = fmaf(uj.y, u3.y, c3); c3 = fmaf(uj.z, u3.z, c3);

        // y = 1 - |c|, clamped (guards |c|>1 rounding; doubles as NaN-safety)
        const float y0 = fmaxf(1.0f - fabsf(c0), 1e-12f);
        const float y1 = fmaxf(1.0f - fabsf(c1), 1e-12f);
        const float y2 = fmaxf(1.0f - fabsf(c2), 1e-12f);
        const float y3 = fmaxf(1.0f - fabsf(c3), 1e-12f);

        const float s0 = y0 * rsqrtf(y0);   // sqrt(y)
        const float s1 = y1 * rsqrtf(y1);
        const float s2 = y2 * rsqrtf(y2);
        const float s3 = y3 * rsqrtf(y3);

        float q0 = fmaf(y0, 0.0187293f, 0.0180731f);
        float q1 = fmaf(y1, 0.0187293f, 0.0180731f);
        float q2 = fmaf(y2, 0.0187293f, 0.0180731f);
        float q3 = fmaf(y3, 0.0187293f, 0.0180731f);
        q0 = fmaf(q0, y0, 0.1197803f);
        q1 = fmaf(q1, y1, 0.1197803f);
        q2 = fmaf(q2, y2, 0.1197803f);
        q3 = fmaf(q3, y3, 0.1197803f);
        q0 = fmaf(q0, y0, 1.4141461f);
        q1 = fmaf(q1, y1, 1.4141461f);
        q2 = fmaf(q2, y2, 1.4141461f);
        q3 = fmaf(q3, y3, 1.4141461f);

        // b = s*q in [0, pi/2]; acos(c) = pi/2 - orsign(pi/2 - b, c)
        const float h0 = fmaf(s0, -q0, HALFPI);   // pi/2 - b  (>= 0)
        const float h1 = fmaf(s1, -q1, HALFPI);
        const float h2 = fmaf(s2, -q2, HALFPI);
        const float h3 = fmaf(s3, -q3, HALFPI);

        float4 v;
        v.x = HALFPI - orsign(h0, c0);
        v.y = HALFPI - orsign(h1, c1);
        v.z = HALFPI - orsign(h2, c2);
        v.w = HALFPI - orsign(h3, c3);

        *reinterpret_cast<float4*>(o) = v;
        o += 8 * N_FIXED;
    }

    // fixups: land after all main-loop stores (same block wrote every address)
    __syncthreads();

    // row j == i (128 floats, 32 threads x float4)
    if (t < 32)
        *reinterpret_cast<float4*>(orow + (size_t)i * N + 4 * t) =
            make_float4(0.0f, 0.0f, 0.0f, 0.0f);
    // column k == i and diagonal j == k
    if (t < N) {
        orow[(size_t)t * N + i] = 0.0f;
        orow[(size_t)t * N + t] = 0.0f;
    }
}

extern "C" void kernel_launch(void* const* d_in, const int* in_sizes, int n_in,
                              void* d_out, int out_size) {
    const float* pos  = (const float*)d_in[0];   // positions (B, N, 3)
    const float* dist = (const float*)d_in[1];   // dist_matrix (B, N, N)
    float* out = (float*)d_out;                  // (B, N, N, N) fp32

    const int N = (int)(3LL * in_sizes[1] / in_sizes[0]);   // = 128
    const int B = in_sizes[0] / (3 * N);                    // = 8

    dim3 grid(N, B);
    angle_kernel<<<grid, 256>>>(pos, dist, out);
}

// round 9
// speedup vs baseline: 1.0628x; 1.0628x over previous
#include <cuda_runtime.h>
#include <cuda_bf16.h>

// AngleTensor: out[b,i,j,k] = mask * arccos( u_ij . u_ik ),  u_ij = (p_j-p_i)/d_ij
// B=8, N=128 fixed.  grid=(N,B), 128 threads/block (one block per (b,i)) —
// the best-benched configuration (R7).
//
// Thread t owns k = 4*(t&31)..+3 (32 contiguous lanes x float4 -> 512B
// coalesced STG per warp); j phase = t>>5, step 4, 32 iters.
// Unroll 8 (32 independent acos chains in flight) attacks the measured
// per-warp dependency stall (~7 cyc/instr); __launch_bounds__(128,8) caps
// regs at 64 to prevent the R5/R6 register blowup.
// Masked entries (row j==i, col k==i, diag j==k) zeroed by post-sync fixup.
// acos: A&S 4.4.45 rebased in y = 1-|c|:  acos(|c|) = sqrt(y)*q(y),
//   q(y) = 1.4141461 + 0.1197803 y + 0.0180731 y^2 + 0.0187293 y^3
// sqrt via MUFU (sqrt.approx.f32); sign via bit-OR (no predicate):
//   b = sqrt(y)*q(y) in [0,pi/2];  acos(c) = pi/2 - orsign(pi/2 - b, c)

#define N_FIXED 128
#define HALFPI  1.57079632679490f

__device__ __forceinline__ float orsign(float v, float c) {
    // v >= 0; returns v with c's sign bit ORed in (one LOP3)
    return __uint_as_float(__float_as_uint(v) | (__float_as_uint(c) & 0x80000000u));
}

__device__ __forceinline__ float sqrt_approx(float x) {
    float r;
    asm("sqrt.approx.f32 %0, %1;" : "=f"(r) : "f"(x));
    return r;
}

__global__ __launch_bounds__(128, 8) void angle_kernel(
    const float* __restrict__ pos,   // (B, N, 3)
    const float* __restrict__ dist,  // (B, N, N)
    float* __restrict__ out)         // (B, N, N, N)
{
    const int i = blockIdx.x;
    const int b = blockIdx.y;
    const int t = threadIdx.x;
    const int N = N_FIXED;

    __shared__ float4 sh[N_FIXED];   // unit vectors

    const float pix = pos[(b * N + i) * 3 + 0];
    const float piy = pos[(b * N + i) * 3 + 1];
    const float piz = pos[(b * N + i) * 3 + 2];

    {
        const int j = t;
        const float px = pos[(b * N + j) * 3 + 0];
        const float py = pos[(b * N + j) * 3 + 1];
        const float pz = pos[(b * N + j) * 3 + 2];
        const float d  = dist[((size_t)b * N + i) * N + j];
        const float inv = (d > 0.0f) ? (1.0f / d) : 0.0f;  // zero vec on j==i
        sh[j] = make_float4((px - pix) * inv, (py - piy) * inv, (pz - piz) * inv, 0.0f);
    }
    __syncthreads();

    const int k0 = (t & 31) * 4;   // owns k0..k0+3
    const int jq = t >> 5;         // j phase (warp-uniform)

    const float4 u0 = sh[k0 + 0];
    const float4 u1 = sh[k0 + 1];
    const float4 u2 = sh[k0 + 2];
    const float4 u3 = sh[k0 + 3];

    float* orow = out + (((size_t)b * N + i) * N) * N;
    float* o = orow + (size_t)jq * N + k0;   // strength-reduced store cursor

#pragma unroll 8
    for (int j = jq; j < N; j += 4) {
        const float4 uj = sh[j];

        float c0 = uj.x * u0.x; c0 = fmaf(uj.y, u0.y, c0); c0 = fmaf(uj.z, u0.z, c0);
        float c1 = uj.x * u1.x; c1 = fmaf(uj.y, u1.y, c1); c1 = fmaf(uj.z, u1.z, c1);
        float c2 = uj.x * u2.x; c2 = fmaf(uj.y, u2.y, c2); c2 = fmaf(uj.z, u2.z, c2);
        float c3 = uj.x * u3.x; c3 = fmaf(uj.y, u3.y, c3); c3 = fmaf(uj.z, u3.z, c3);

        // y = 1 - |c|, clamped (guards |c|>1 rounding; doubles as NaN-safety)
        const float y0 = fmaxf(1.0f - fabsf(c0), 1e-12f);
        const float y1 = fmaxf(1.0f - fabsf(c1), 1e-12f);
        const float y2 = fmaxf(1.0f - fabsf(c2), 1e-12f);
        const float y3 = fmaxf(1.0f - fabsf(c3), 1e-12f);

        const float s0 = sqrt_approx(y0);   // one MUFU, no trailing FMUL
        const float s1 = sqrt_approx(y1);
        const float s2 = sqrt_approx(y2);
        const float s3 = sqrt_approx(y3);

        float q0 = fmaf(y0, 0.0187293f, 0.0180731f);
        float q1 = fmaf(y1, 0.0187293f, 0.0180731f);
        float q2 = fmaf(y2, 0.0187293f, 0.0180731f);
        float q3 = fmaf(y3, 0.0187293f, 0.0180731f);
        q0 = fmaf(q0, y0, 0.1197803f);
        q1 = fmaf(q1, y1, 0.1197803f);
        q2 = fmaf(q2, y2, 0.1197803f);
        q3 = fmaf(q3, y3, 0.1197803f);
        q0 = fmaf(q0, y0, 1.4141461f);
        q1 = fmaf(q1, y1, 1.4141461f);
        q2 = fmaf(q2, y2, 1.4141461f);
        q3 = fmaf(q3, y3, 1.4141461f);

        // h = pi/2 - s*q  (>= 0);  acos(c) = pi/2 - orsign(h, c)
        const float h0 = fmaf(s0, -q0, HALFPI);
        const float h1 = fmaf(s1, -q1, HALFPI);
        const float h2 = fmaf(s2, -q2, HALFPI);
        const float h3 = fmaf(s3, -q3, HALFPI);

        float4 v;
        v.x = HALFPI - orsign(h0, c0);
        v.y = HALFPI - orsign(h1, c1);
        v.z = HALFPI - orsign(h2, c2);
        v.w = HALFPI - orsign(h3, c3);

        *reinterpret_cast<float4*>(o) = v;
        o += 4 * N_FIXED;
    }

    // fixups: land after all main-loop stores (same block wrote every address)
    __syncthreads();

    // row j == i (128 floats, 32 threads x float4)
    if (t < 32)
        *reinterpret_cast<float4*>(orow + (size_t)i * N + 4 * t) =
            make_float4(0.0f, 0.0f, 0.0f, 0.0f);
    // column k == i and diagonal j == k
    orow[(size_t)t * N + i] = 0.0f;
    orow[(size_t)t * N + t] = 0.0f;
}

extern "C" void kernel_launch(void* const* d_in, const int* in_sizes, int n_in,
                              void* d_out, int out_size) {
    const float* pos  = (const float*)d_in[0];   // positions (B, N, 3)
    const float* dist = (const float*)d_in[1];   // dist_matrix (B, N, N)
    float* out = (float*)d_out;                  // (B, N, N, N) fp32

    const int N = (int)(3LL * in_sizes[1] / in_sizes[0]);   // = 128
    const int B = in_sizes[0] / (3 * N);                    // = 8

    dim3 grid(N, B);
    angle_kernel<<<grid, 128>>>(pos, dist, out);
}

// round 10
// speedup vs baseline: 1.1079x; 1.0424x over previous
#include <cuda_runtime.h>
#include <cuda_bf16.h>

// AngleTensor: out[b,i,j,k] = mask * arccos( u_ij . u_ik ),  u_ij = (p_j-p_i)/d_ij
// B=8, N=128 fixed.  grid=(N,B), 128 threads/block (one block per (b,i)).
//
// Proven R7 execution shape: thread t owns k = 4*(t&31)..+3 (32 contiguous
// lanes x float4 -> 512B coalesced STG per warp); j = (t>>5) step 4, 32 iters,
// unroll 4, regs ~40. Masked entries (row j==i, col k==i, diag j==k) zeroed by
// post-sync fixup.
// acos: A&S 4.4.45 rebased in y = 1-|c|:  acos(|c|) = sqrt(y)*q(y),
//   q(y) = 1.4141461 + 0.1197803 y + 0.0180731 y^2 + 0.0187293 y^3
// Trims vs R7:
//  - sqrt via MUFU sqrt.approx.f32 (no trailing FMUL)
//  - clamp FMNMX deleted: y = 1.0000002 - |c| (bias 2e-7 keeps y > 0 even when
//    rounding pushes |c| slightly above 1; adds <=1.4e-5 rad for y>=1e-4)
//  - sign via bit-OR: b in [0,pi/2]; acos(c) = pi/2 - orsign(pi/2 - b, c)

#define N_FIXED 128
#define HALFPI  1.57079632679490f
#define ONE_EPS 1.0000002f

__device__ __forceinline__ float orsign(float v, float c) {
    // v >= 0; returns v with c's sign bit ORed in (one LOP3)
    return __uint_as_float(__float_as_uint(v) | (__float_as_uint(c) & 0x80000000u));
}

__device__ __forceinline__ float sqrt_approx(float x) {
    float r;
    asm("sqrt.approx.f32 %0, %1;" : "=f"(r) : "f"(x));
    return r;
}

__global__ __launch_bounds__(128) void angle_kernel(
    const float* __restrict__ pos,   // (B, N, 3)
    const float* __restrict__ dist,  // (B, N, N)
    float* __restrict__ out)         // (B, N, N, N)
{
    const int i = blockIdx.x;
    const int b = blockIdx.y;
    const int t = threadIdx.x;
    const int N = N_FIXED;

    __shared__ float4 sh[N_FIXED];   // unit vectors

    const float pix = pos[(b * N + i) * 3 + 0];
    const float piy = pos[(b * N + i) * 3 + 1];
    const float piz = pos[(b * N + i) * 3 + 2];

    {
        const int j = t;
        const float px = pos[(b * N + j) * 3 + 0];
        const float py = pos[(b * N + j) * 3 + 1];
        const float pz = pos[(b * N + j) * 3 + 2];
        const float d  = dist[((size_t)b * N + i) * N + j];
        const float inv = (d > 0.0f) ? (1.0f / d) : 0.0f;  // zero vec on j==i
        sh[j] = make_float4((px - pix) * inv, (py - piy) * inv, (pz - piz) * inv, 0.0f);
    }
    __syncthreads();

    const int k0 = (t & 31) * 4;   // owns k0..k0+3
    const int jq = t >> 5;         // j phase (warp-uniform)

    const float4 u0 = sh[k0 + 0];
    const float4 u1 = sh[k0 + 1];
    const float4 u2 = sh[k0 + 2];
    const float4 u3 = sh[k0 + 3];

    float* orow = out + (((size_t)b * N + i) * N) * N;
    float* o = orow + (size_t)jq * N + k0;   // strength-reduced store cursor

#pragma unroll 4
    for (int j = jq; j < N; j += 4) {
        const float4 uj = sh[j];

        float c0 = uj.x * u0.x; c0 = fmaf(uj.y, u0.y, c0); c0 = fmaf(uj.z, u0.z, c0);
        float c1 = uj.x * u1.x; c1 = fmaf(uj.y, u1.y, c1); c1 = fmaf(uj.z, u1.z, c1);
        float c2 = uj.x * u2.x; c2 = fmaf(uj.y, u2.y, c2); c2 = fmaf(uj.z, u2.z, c2);
        float c3 = uj.x * u3.x; c3 = fmaf(uj.y, u3.y, c3); c3 = fmaf(uj.z, u3.z, c3);

        // y = (1+2e-7) - |c|  > 0 always (no clamp instruction needed)
        const float y0 = ONE_EPS - fabsf(c0);
        const float y1 = ONE_EPS - fabsf(c1);
        const float y2 = ONE_EPS - fabsf(c2);
        const float y3 = ONE_EPS - fabsf(c3);

        const float s0 = sqrt_approx(y0);   // one MUFU
        const float s1 = sqrt_approx(y1);
        const float s2 = sqrt_approx(y2);
        const float s3 = sqrt_approx(y3);

        float q0 = fmaf(y0, 0.0187293f, 0.0180731f);
        float q1 = fmaf(y1, 0.0187293f, 0.0180731f);
        float q2 = fmaf(y2, 0.0187293f, 0.0180731f);
        float q3 = fmaf(y3, 0.0187293f, 0.0180731f);
        q0 = fmaf(q0, y0, 0.1197803f);
        q1 = fmaf(q1, y1, 0.1197803f);
        q2 = fmaf(q2, y2, 0.1197803f);
        q3 = fmaf(q3, y3, 0.1197803f);
        q0 = fmaf(q0, y0, 1.4141461f);
        q1 = fmaf(q1, y1, 1.4141461f);
        q2 = fmaf(q2, y2, 1.4141461f);
        q3 = fmaf(q3, y3, 1.4141461f);

        // h = pi/2 - s*q  (>= 0);  acos(c) = pi/2 - orsign(h, c)
        const float h0 = fmaf(s0, -q0, HALFPI);
        const float h1 = fmaf(s1, -q1, HALFPI);
        const float h2 = fmaf(s2, -q2, HALFPI);
        const float h3 = fmaf(s3, -q3, HALFPI);

        float4 v;
        v.x = HALFPI - orsign(h0, c0);
        v.y = HALFPI - orsign(h1, c1);
        v.z = HALFPI - orsign(h2, c2);
        v.w = HALFPI - orsign(h3, c3);

        *reinterpret_cast<float4*>(o) = v;
        o += 4 * N_FIXED;
    }

    // fixups: land after all main-loop stores (same block wrote every address)
    __syncthreads();

    // row j == i (128 floats, 32 threads x float4)
    if (t < 32)
        *reinterpret_cast<float4*>(orow + (size_t)i * N + 4 * t) =
            make_float4(0.0f, 0.0f, 0.0f, 0.0f);
    // column k == i and diagonal j == k
    orow[(size_t)t * N + i] = 0.0f;
    orow[(size_t)t * N + t] = 0.0f;
}

extern "C" void kernel_launch(void* const* d_in, const int* in_sizes, int n_in,
                              void* d_out, int out_size) {
    const float* pos  = (const float*)d_in[0];   // positions (B, N, 3)
    const float* dist = (const float*)d_in[1];   // dist_matrix (B, N, N)
    float* out = (float*)d_out;                  // (B, N, N, N) fp32

    const int N = (int)(3LL * in_sizes[1] / in_sizes[0]);   // = 128
    const int B = in_sizes[0] / (3 * N);                    // = 8

    dim3 grid(N, B);
    angle_kernel<<<grid, 128>>>(pos, dist, out);
}